// round 8
// baseline (speedup 1.0000x reference)
#include <cuda_runtime.h>
#include <math.h>

#define Bn 2
#define Cn 21
#define Hn 512
#define Wn 512
#define HL 128
#define WL 128
#define Kn 11
#define SPANn 5
#define KKn 121

// padded pooled-pred buffer: [b][c][144][144], origin (5,8)
#define PP 144
#define XOFF 5
#define YOFF 8
#define PLANE (PP*PP)

// gk smem layout: word = pix + (pix>>5)*4  (4-word pad per 32 -> conflict-free LDS.128)
#define GKROW2 288
#define GKIDX(pix) ((pix) + (((pix) >> 5) << 2))
#define GK_SMEM_BYTES (KKn * GKROW2 * 4)

__device__ float g_ppad [Bn*Cn*PLANE];          // pooled pred, zero-padded halo
__device__ float g_msg  [Bn*Cn*HL*WL];          // low-res message
__device__ float g_gk   [Bn*8*8*KKn*256];       // gauss kernel, tiled [b][tx][ty][ij][16x16 pix]

__constant__ float c_wtab[4] = {0.375f, 0.125f, 0.875f, 0.625f};

// ---------------------------------------------------------------------------
// 0) zero the padded pooled buffer
__global__ void k_zero() {
    int idx = blockIdx.x * 256 + threadIdx.x;
    if (idx < Bn*Cn*PLANE/4) ((float4*)g_ppad)[idx] = make_float4(0.f,0.f,0.f,0.f);
}

// ---------------------------------------------------------------------------
// 2) merged gauss kernel with fused img pooling, tiled per 16x16 pixel block
__global__ void k_gauss(const float* __restrict__ img,
                        const float* __restrict__ col_schan,
                        const float* __restrict__ pos_sdims,
                        const float* __restrict__ pos_compat,
                        const float* __restrict__ col_compat) {
    __shared__ float cf_s[3][26*26];
    __shared__ float pos_s[KKn];
    int tyi = blockIdx.x, txi = blockIdx.y, b = blockIdx.z;
    int t = threadIdx.x;
    int x0 = txi*16 - SPANn, y0 = tyi*16 - SPANn;
    if (t < KKn) {
        int i = t / 11, j = t - i*11;
        int dx = i - SPANn, dy = j - SPANn;
        float sd4 = 4.f * pos_sdims[0];
        float dpos2 = sd4*sd4 * (float)(dx*dx + dy*dy);
        pos_s[t] = pos_compat[0] * __expf(-0.5f*dpos2);
    }
    float pscale = col_schan[0] * 0.0625f;
    // pool img halo on the fly: 3*676 pooled cells, each = 4x4 img avg
    for (int i = t; i < 3*676; i += 256) {
        int c = i / 676, rem = i % 676;
        int xx = x0 + rem/26, yy = y0 + rem%26;
        float v = 0.f;
        if ((unsigned)xx < HL && (unsigned)yy < WL) {
            const float* src = img + ((size_t)(b*3 + c)*Hn + xx*4)*Wn + yy*4;
            float s = 0.f;
            #pragma unroll
            for (int a = 0; a < 4; a++) {
                float4 q = __ldg((const float4*)(src + a*Wn));
                s += q.x + q.y + q.z + q.w;
            }
            v = s * pscale;
        }
        cf_s[c][rem] = v;
    }
    __syncthreads();
    int px = t >> 4, py = t & 15;
    int ctr = (px + SPANn)*26 + (py + SPANn);
    float c0 = cf_s[0][ctr], c1 = cf_s[1][ctr], c2 = cf_s[2][ctr];
    float cc = col_compat[0];
    int gx = txi*16 + px, gy = tyi*16 + py;
    float* outb = g_gk + (size_t)(((b*8 + txi)*8 + tyi)*KKn)*256 + t;
    #pragma unroll 1
    for (int ij = 0; ij < KKn; ij++) {
        int i = ij / 11, j = ij - i*11;
        int dx = i - SPANn, dy = j - SPANn;
        bool valid = ((unsigned)(gx + dx) < HL) && ((unsigned)(gy + dy) < WL);
        int si = (px + i)*26 + (py + j);
        float d0 = cf_s[0][si] - c0;
        float d1 = cf_s[1][si] - c1;
        float d2 = cf_s[2][si] - c2;
        float dcol2 = d0*d0 + d1*d1 + d2*d2;
        float gval = valid ? (pos_s[ij] + cc * __expf(-0.5f*dcol2)) : 0.f;
        outb[ij*256] = gval;
    }
}

// ---------------------------------------------------------------------------
// 3) pooled init pred = avg_pool(log_softmax(unary)) -> g_ppad
//    Row-pair preloading for 2x MLP.
__global__ void k_init(const float* __restrict__ unary) {
    int b = blockIdx.z;
    int w = threadIdx.x >> 5, l = threadIdx.x & 31;
    int x0 = blockIdx.y*32 + w*4;
    int Y  = blockIdx.x*32 + l;
    const float* up = unary + ((size_t)(b*Cn)*Hn + x0)*Wn + Y;
    float pool[Cn];
    #pragma unroll
    for (int c = 0; c < Cn; c++) pool[c] = 0.f;
    #pragma unroll
    for (int h = 0; h < 2; h++) {
        float u0[Cn], u1[Cn];
        #pragma unroll
        for (int c = 0; c < Cn; c++) {
            u0[c] = __ldg(up + (size_t)c*Hn*Wn + (2*h  )*Wn);
            u1[c] = __ldg(up + (size_t)c*Hn*Wn + (2*h+1)*Wn);
        }
        float m0 = -1e30f, m1 = -1e30f;
        #pragma unroll
        for (int c = 0; c < Cn; c++) { m0 = fmaxf(m0, u0[c]); m1 = fmaxf(m1, u1[c]); }
        float s0 = 0.f, s1 = 0.f;
        #pragma unroll
        for (int c = 0; c < Cn; c++) { s0 += __expf(u0[c] - m0); s1 += __expf(u1[c] - m1); }
        float lse0 = m0 + logf(s0), lse1 = m1 + logf(s1);
        float lsum = lse0 + lse1;
        #pragma unroll
        for (int c = 0; c < Cn; c++) pool[c] += (u0[c] + u1[c]) - lsum;
    }
    int xp = (x0 >> 2) + XOFF;
    int yp = (Y  >> 2) + YOFF;
    #pragma unroll
    for (int c = 0; c < Cn; c++) {
        float r = pool[c];
        r += __shfl_xor_sync(0xffffffffu, r, 1);
        r += __shfl_xor_sync(0xffffffffu, r, 2);
        if ((l & 3) == 0)
            g_ppad[((size_t)(b*Cn + c)*PP + xp)*PP + yp] = r * 0.0625f;
    }
}

// ---------------------------------------------------------------------------
// 4) message passing: full gk tile staged once in 139KB smem (exact R6)
__global__ void k_msg() {
    extern __shared__ float gk_s[];           // [121][288] padded
    const int t = threadIdx.x;
    const int b = blockIdx.z;
    const int tyi = blockIdx.x, txi = blockIdx.y;
    const int chunk = t >> 5, lane = t & 31;
    const int pxrow = lane >> 1, cg = lane & 1;
    const int pxg = txi*16 + pxrow;
    const int Yb  = tyi*16 + cg*8;
    const float* gbase = g_gk + (size_t)(((b*8 + txi)*8 + tyi)*KKn)*256;

    {
        const float4* src = (const float4*)gbase;
        #pragma unroll 4
        for (int idx = t; idx < KKn*64; idx += 224) {
            int ij = idx >> 6, pq = idx & 63;
            float4 v = __ldg(src + idx);
            *(float4*)(&gk_s[ij*GKROW2 + GKIDX(pq*4)]) = v;
        }
    }
    __syncthreads();

    float acc[3][8];
    #pragma unroll
    for (int c = 0; c < 3; c++)
        #pragma unroll
        for (int k = 0; k < 8; k++) acc[c][k] = 0.f;

    const int gkoff = GKIDX(lane*8);

    #pragma unroll 1
    for (int i = 0; i < 11; i++) {
        float pr[3][24];
        #pragma unroll
        for (int c = 0; c < 3; c++) {
            const float4* pp = (const float4*)(g_ppad +
                ((size_t)(b*Cn + chunk*3 + c)*PP + (pxg + i))*PP + Yb);
            #pragma unroll
            for (int q = 0; q < 6; q++) {
                float4 v = __ldg(pp + q);
                pr[c][q*4+0] = v.x; pr[c][q*4+1] = v.y;
                pr[c][q*4+2] = v.z; pr[c][q*4+3] = v.w;
            }
        }
        const float* gs = gk_s + i*11*GKROW2 + gkoff;
        #pragma unroll
        for (int j = 0; j < 11; j++) {
            float4 ga = *(const float4*)(gs + j*GKROW2);
            float4 gb = *(const float4*)(gs + j*GKROW2 + 4);
            float gv[8] = {ga.x, ga.y, ga.z, ga.w, gb.x, gb.y, gb.z, gb.w};
            #pragma unroll
            for (int c = 0; c < 3; c++)
                #pragma unroll
                for (int k = 0; k < 8; k++)
                    acc[c][k] += gv[k] * pr[c][k + j + 3];
        }
    }

    #pragma unroll
    for (int c = 0; c < 3; c++) {
        float* mp = g_msg + ((size_t)(b*Cn + chunk*3 + c)*HL + pxg)*WL + Yb;
        *(float4*)mp       = make_float4(acc[c][0], acc[c][1], acc[c][2], acc[c][3]);
        *(float4*)(mp + 4) = make_float4(acc[c][4], acc[c][5], acc[c][6], acc[c][7]);
    }
}

// ---------------------------------------------------------------------------
// 5) fused iter: softmax((1-w)*unary + w*up(msg)) pooled -> g_ppad
//    Row-pair preloading for 2x MLP.
__global__ void k_iter(const float* __restrict__ unary, const float* __restrict__ weight) {
    __shared__ float m_s[Cn*100];   // [c][10][10]
    int b = blockIdx.z;
    int t = threadIdx.x, w = t >> 5, l = t & 31;
    int lx0 = blockIdx.y*8 - 1, ly0 = blockIdx.x*8 - 1;
    for (int i = t; i < Cn*100; i += 256) {
        int c = i / 100, rem = i % 100;
        int xx = lx0 + rem/10; xx = max(0, min(HL-1, xx));
        int yy = ly0 + rem%10; yy = max(0, min(WL-1, yy));
        m_s[i] = g_msg[((b*Cn + c)*HL + xx)*WL + yy];
    }
    __syncthreads();
    int x0 = blockIdx.y*32 + w*4;
    int Y  = blockIdx.x*32 + l;
    const float* up = unary + ((size_t)(b*Cn)*Hn + x0)*Wn + Y;
    float wgt = weight[0], uw = 1.f - wgt;
    int ry = l & 3;
    float wy0 = c_wtab[ry], wy1 = 1.f - wy0;
    int yA = (l >> 2) + 1 + ((ry < 2) ? -1 : 0);
    float pool[Cn];
    #pragma unroll
    for (int c = 0; c < Cn; c++) pool[c] = 0.f;
    #pragma unroll
    for (int h = 0; h < 2; h++) {
        float u0[Cn], u1[Cn];
        #pragma unroll
        for (int c = 0; c < Cn; c++) {
            u0[c] = __ldg(up + (size_t)c*Hn*Wn + (2*h  )*Wn);
            u1[c] = __ldg(up + (size_t)c*Hn*Wn + (2*h+1)*Wn);
        }
        #pragma unroll
        for (int r2 = 0; r2 < 2; r2++) {
            int r = 2*h + r2;
            float wx0 = c_wtab[r], wx1 = 1.f - wx0;
            int xA = w + 1 + ((r < 2) ? -1 : 0);
            int base = xA*10 + yA;
            float v[Cn];
            float mmax = -1e30f;
            #pragma unroll
            for (int c = 0; c < Cn; c++) {
                const float* mc = m_s + c*100 + base;
                float mu = wx0*(wy0*mc[0] + wy1*mc[1]) + wx1*(wy0*mc[10] + wy1*mc[11]);
                float uv = r2 ? u1[c] : u0[c];
                float vv = uw * uv + wgt * mu;
                v[c] = vv;
                mmax = fmaxf(mmax, vv);
            }
            float s = 0.f;
            #pragma unroll
            for (int c = 0; c < Cn; c++) { v[c] = __expf(v[c] - mmax); s += v[c]; }
            float inv = 1.f / s;
            #pragma unroll
            for (int c = 0; c < Cn; c++) pool[c] += v[c] * inv;
        }
    }
    int xp = (x0 >> 2) + XOFF;
    int yp = (Y  >> 2) + YOFF;
    #pragma unroll
    for (int c = 0; c < Cn; c++) {
        float r = pool[c];
        r += __shfl_xor_sync(0xffffffffu, r, 1);
        r += __shfl_xor_sync(0xffffffffu, r, 2);
        if ((l & 3) == 0)
            g_ppad[((size_t)(b*Cn + c)*PP + xp)*PP + yp] = r * 0.0625f;
    }
}

// ---------------------------------------------------------------------------
// 6) final: recompute lse from unary, write (1-w)*(u-lse) + w*up(msg)
//    Row-pair preloading.
__global__ void k_final(const float* __restrict__ unary, const float* __restrict__ weight,
                        float* __restrict__ out) {
    __shared__ float m_s[Cn*100];
    int b = blockIdx.z;
    int t = threadIdx.x, w = t >> 5, l = t & 31;
    int lx0 = blockIdx.y*8 - 1, ly0 = blockIdx.x*8 - 1;
    for (int i = t; i < Cn*100; i += 256) {
        int c = i / 100, rem = i % 100;
        int xx = lx0 + rem/10; xx = max(0, min(HL-1, xx));
        int yy = ly0 + rem%10; yy = max(0, min(WL-1, yy));
        m_s[i] = g_msg[((b*Cn + c)*HL + xx)*WL + yy];
    }
    __syncthreads();
    int x0 = blockIdx.y*32 + w*4;
    int Y  = blockIdx.x*32 + l;
    const float* up   = unary + ((size_t)(b*Cn)*Hn + x0)*Wn + Y;
    float*       outp = out   + ((size_t)(b*Cn)*Hn + x0)*Wn + Y;
    float wgt = weight[0], uw = 1.f - wgt;
    int ry = l & 3;
    float wy0 = c_wtab[ry], wy1 = 1.f - wy0;
    int yA = (l >> 2) + 1 + ((ry < 2) ? -1 : 0);
    #pragma unroll
    for (int h = 0; h < 2; h++) {
        float u0[Cn], u1[Cn];
        #pragma unroll
        for (int c = 0; c < Cn; c++) {
            u0[c] = __ldg(up + (size_t)c*Hn*Wn + (2*h  )*Wn);
            u1[c] = __ldg(up + (size_t)c*Hn*Wn + (2*h+1)*Wn);
        }
        float m0 = -1e30f, m1 = -1e30f;
        #pragma unroll
        for (int c = 0; c < Cn; c++) { m0 = fmaxf(m0, u0[c]); m1 = fmaxf(m1, u1[c]); }
        float s0 = 0.f, s1 = 0.f;
        #pragma unroll
        for (int c = 0; c < Cn; c++) { s0 += __expf(u0[c] - m0); s1 += __expf(u1[c] - m1); }
        float lse0 = m0 + logf(s0), lse1 = m1 + logf(s1);
        #pragma unroll
        for (int r2 = 0; r2 < 2; r2++) {
            int r = 2*h + r2;
            float wx0 = c_wtab[r], wx1 = 1.f - wx0;
            int xA = w + 1 + ((r < 2) ? -1 : 0);
            int base = xA*10 + yA;
            float lse = r2 ? lse1 : lse0;
            #pragma unroll
            for (int c = 0; c < Cn; c++) {
                const float* mc = m_s + c*100 + base;
                float mu = wx0*(wy0*mc[0] + wy1*mc[1]) + wx1*(wy0*mc[10] + wy1*mc[11]);
                float uv = r2 ? u1[c] : u0[c];
                outp[(size_t)c*Hn*Wn + r*Wn] = uw * (uv - lse) + wgt * mu;
            }
        }
    }
}

// ---------------------------------------------------------------------------
extern "C" void kernel_launch(void* const* d_in, const int* in_sizes, int n_in,
                              void* d_out, int out_size) {
    const float* unary      = (const float*)d_in[0];
    const float* img        = (const float*)d_in[1];
    const float* pos_sdims  = (const float*)d_in[2];
    const float* col_schan  = (const float*)d_in[3];
    const float* pos_compat = (const float*)d_in[4];
    const float* col_compat = (const float*)d_in[5];
    const float* weight     = (const float*)d_in[6];
    float* out = (float*)d_out;

    static int smem_set = 0;
    if (!smem_set) {
        cudaFuncSetAttribute(k_msg, cudaFuncAttributeMaxDynamicSharedMemorySize,
                             GK_SMEM_BYTES);
        smem_set = 1;
    }

    k_zero<<<(Bn*Cn*PLANE/4 + 255)/256, 256>>>();
    k_gauss<<<dim3(8, 8, Bn), 256>>>(img, col_schan, pos_sdims, pos_compat, col_compat);
    k_init<<<dim3(16, 16, Bn), 256>>>(unary);
    for (int it = 0; it < 5; it++) {
        k_msg<<<dim3(8, 8, Bn), 224, GK_SMEM_BYTES>>>();
        if (it < 4)
            k_iter<<<dim3(16, 16, Bn), 256>>>(unary, weight);
        else
            k_final<<<dim3(16, 16, Bn), 256>>>(unary, weight, out);
    }
}

// round 9
// speedup vs baseline: 1.1897x; 1.1897x over previous
#include <cuda_runtime.h>
#include <math.h>

#define Bn 2
#define Cn 21
#define Hn 512
#define Wn 512
#define HL 128
#define WL 128
#define Kn 11
#define SPANn 5
#define KKn 121

// padded pooled-pred buffer: [b][c][144][144], origin (5,8)
#define PP 144
#define XOFF 5
#define YOFF 8
#define PLANE (PP*PP)

// gk tile: 8x16 pixels, [b][tx16][ty8][ij121][128]
#define GK_TILE 128
#define GK_SMEM_BYTES (KKn * GK_TILE * 4)

__device__ float g_ppad [Bn*Cn*PLANE];          // pooled pred, zero-padded halo
__device__ float g_msg  [Bn*Cn*HL*WL];          // low-res message
__device__ float g_cf   [Bn*3*HL*WL];           // pooled color feats
__device__ float g_gk   [Bn*16*8*KKn*GK_TILE];  // gauss kernel, tiled per 8x16 block

__constant__ float c_wtab[4] = {0.375f, 0.125f, 0.875f, 0.625f};

// ---------------------------------------------------------------------------
// 0) zero the padded pooled buffer
__global__ void k_zero() {
    int idx = blockIdx.x * 256 + threadIdx.x;
    if (idx < Bn*Cn*PLANE/4) ((float4*)g_ppad)[idx] = make_float4(0.f,0.f,0.f,0.f);
}

// ---------------------------------------------------------------------------
// 1) pooled color features: avg_pool(img * schan, 4)  (exact R7)
__global__ void k_pool_img(const float* __restrict__ img, const float* __restrict__ schan) {
    int idx = blockIdx.x * 256 + threadIdx.x;
    if (idx >= Bn*3*HL*WL) return;
    int y = idx & (WL-1);
    int x = (idx >> 7) & (HL-1);
    int c = (idx >> 14) % 3;
    int b = idx / (3*HL*WL);
    const float* src = img + ((b*3 + c)*Hn + x*4)*Wn + y*4;
    float s = 0.f;
    #pragma unroll
    for (int i = 0; i < 4; i++)
        #pragma unroll
        for (int j = 0; j < 4; j++) s += src[i*Wn + j];
    g_cf[idx] = s * (schan[0] * 0.0625f);
}

// ---------------------------------------------------------------------------
// 2) merged gauss kernel, tiled per 8x16 pixel block: [b][tx][ty][ij][128]
//    128 threads, one pixel each.
__global__ void k_gauss(const float* __restrict__ pos_sdims,
                        const float* __restrict__ pos_compat,
                        const float* __restrict__ col_compat) {
    __shared__ float cf_s[3][18*26];
    __shared__ float pos_s[KKn];
    int tyi = blockIdx.x, txi = blockIdx.y, b = blockIdx.z;
    int t = threadIdx.x;
    int x0 = txi*8 - SPANn, y0 = tyi*16 - SPANn;
    if (t < KKn) {
        int i = t / 11, j = t - i*11;
        int dx = i - SPANn, dy = j - SPANn;
        float sd4 = 4.f * pos_sdims[0];
        float dpos2 = sd4*sd4 * (float)(dx*dx + dy*dy);
        pos_s[t] = pos_compat[0] * __expf(-0.5f*dpos2);
    }
    for (int i = t; i < 3*468; i += 128) {
        int c = i / 468, rem = i % 468;
        int xx = x0 + rem/26, yy = y0 + rem%26;
        float v = 0.f;
        if ((unsigned)xx < HL && (unsigned)yy < WL)
            v = g_cf[((b*3 + c)*HL + xx)*WL + yy];
        cf_s[c][rem] = v;
    }
    __syncthreads();
    int px = t >> 4, py = t & 15;
    int ctr = (px + SPANn)*26 + (py + SPANn);
    float c0 = cf_s[0][ctr], c1 = cf_s[1][ctr], c2 = cf_s[2][ctr];
    float cc = col_compat[0];
    int gx = txi*8 + px, gy = tyi*16 + py;
    float* outb = g_gk + (size_t)(((b*16 + txi)*8 + tyi)*KKn)*GK_TILE + t;
    #pragma unroll 1
    for (int ij = 0; ij < KKn; ij++) {
        int i = ij / 11, j = ij - i*11;
        int dx = i - SPANn, dy = j - SPANn;
        bool valid = ((unsigned)(gx + dx) < HL) && ((unsigned)(gy + dy) < WL);
        int si = (px + i)*26 + (py + j);
        float d0 = cf_s[0][si] - c0;
        float d1 = cf_s[1][si] - c1;
        float d2 = cf_s[2][si] - c2;
        float dcol2 = d0*d0 + d1*d1 + d2*d2;
        float gval = valid ? (pos_s[ij] + cc * __expf(-0.5f*dcol2)) : 0.f;
        outb[ij*GK_TILE] = gval;
    }
}

// ---------------------------------------------------------------------------
// 3) pooled init pred (exact R7)
__global__ void k_init(const float* __restrict__ unary) {
    int b = blockIdx.z;
    int w = threadIdx.x >> 5, l = threadIdx.x & 31;
    int x0 = blockIdx.y*32 + w*4;
    int Y  = blockIdx.x*32 + l;
    const float* up = unary + ((size_t)(b*Cn)*Hn + x0)*Wn + Y;
    float pool[Cn];
    #pragma unroll
    for (int c = 0; c < Cn; c++) pool[c] = 0.f;
    #pragma unroll
    for (int r = 0; r < 4; r++) {
        float u[Cn];
        float m = -1e30f;
        #pragma unroll
        for (int c = 0; c < Cn; c++) {
            u[c] = __ldg(up + (size_t)c*Hn*Wn + r*Wn);
            m = fmaxf(m, u[c]);
        }
        float s = 0.f;
        #pragma unroll
        for (int c = 0; c < Cn; c++) s += __expf(u[c] - m);
        float lse = m + logf(s);
        #pragma unroll
        for (int c = 0; c < Cn; c++) pool[c] += u[c] - lse;
    }
    int xp = (x0 >> 2) + XOFF;
    int yp = (Y  >> 2) + YOFF;
    #pragma unroll
    for (int c = 0; c < Cn; c++) {
        float r = pool[c];
        r += __shfl_xor_sync(0xffffffffu, r, 1);
        r += __shfl_xor_sync(0xffffffffu, r, 2);
        if ((l & 3) == 0)
            g_ppad[((size_t)(b*Cn + c)*PP + xp)*PP + yp] = r * 0.0625f;
    }
}

// ---------------------------------------------------------------------------
// 4) message passing: 8x16 tile, 62KB gk smem, 3 blocks/SM, 256 blocks.
//    224 threads: chunk = t>>5 (7 chunks x 3 channels), lane = 8 xrows x 4 ygroups
__global__ __launch_bounds__(224) void k_msg() {
    extern __shared__ float gk_s[];           // [121][128]
    const int t = threadIdx.x;
    const int b = blockIdx.z;
    const int tyi = blockIdx.x, txi = blockIdx.y;
    const int chunk = t >> 5, lane = t & 31;
    const int xrow = lane >> 2, yg = lane & 3;
    const int pxg = txi*8 + xrow;
    const int Yb  = tyi*16 + yg*4;            // output col base (unpadded coords)
    const float* gbase = g_gk + (size_t)(((b*16 + txi)*8 + tyi)*KKn)*GK_TILE;

    // stage gk tile (121*32 float4s) once
    {
        const float4* src = (const float4*)gbase;
        #pragma unroll 4
        for (int idx = t; idx < KKn*32; idx += 224) {
            ((float4*)gk_s)[idx] = __ldg(src + idx);
        }
    }
    __syncthreads();

    float acc[3][4];
    #pragma unroll
    for (int c = 0; c < 3; c++)
        #pragma unroll
        for (int k = 0; k < 4; k++) acc[c][k] = 0.f;

    const int pix = lane*4;                   // this thread's 4 pixels in the 128-tile
    // pr window: padded cols [Yb-8+YOFF, Yb+12+YOFF) = [Yb, Yb+20) in padded idx
    #pragma unroll 1
    for (int i = 0; i < 11; i++) {
        float pr[3][20];
        #pragma unroll
        for (int c = 0; c < 3; c++) {
            const float4* pp = (const float4*)(g_ppad +
                ((size_t)(b*Cn + chunk*3 + c)*PP + (pxg + i))*PP + Yb);
            #pragma unroll
            for (int q = 0; q < 5; q++) {
                float4 v = __ldg(pp + q);
                pr[c][q*4+0] = v.x; pr[c][q*4+1] = v.y;
                pr[c][q*4+2] = v.z; pr[c][q*4+3] = v.w;
            }
        }
        const float* gs = gk_s + i*11*GK_TILE + pix;
        #pragma unroll
        for (int j = 0; j < 11; j++) {
            float4 gv = *(const float4*)(gs + j*GK_TILE);
            #pragma unroll
            for (int c = 0; c < 3; c++) {
                acc[c][0] += gv.x * pr[c][0 + j + 3];
                acc[c][1] += gv.y * pr[c][1 + j + 3];
                acc[c][2] += gv.z * pr[c][2 + j + 3];
                acc[c][3] += gv.w * pr[c][3 + j + 3];
            }
        }
    }

    #pragma unroll
    for (int c = 0; c < 3; c++) {
        float* mp = g_msg + ((size_t)(b*Cn + chunk*3 + c)*HL + pxg)*WL + Yb;
        *(float4*)mp = make_float4(acc[c][0], acc[c][1], acc[c][2], acc[c][3]);
    }
}

// ---------------------------------------------------------------------------
// 5) fused iter (exact R7)
__global__ void k_iter(const float* __restrict__ unary, const float* __restrict__ weight) {
    __shared__ float m_s[Cn*100];   // [c][10][10]
    int b = blockIdx.z;
    int t = threadIdx.x, w = t >> 5, l = t & 31;
    int lx0 = blockIdx.y*8 - 1, ly0 = blockIdx.x*8 - 1;
    for (int i = t; i < Cn*100; i += 256) {
        int c = i / 100, rem = i % 100;
        int xx = lx0 + rem/10; xx = max(0, min(HL-1, xx));
        int yy = ly0 + rem%10; yy = max(0, min(WL-1, yy));
        m_s[i] = g_msg[((b*Cn + c)*HL + xx)*WL + yy];
    }
    __syncthreads();
    int x0 = blockIdx.y*32 + w*4;
    int Y  = blockIdx.x*32 + l;
    const float* up = unary + ((size_t)(b*Cn)*Hn + x0)*Wn + Y;
    float wgt = weight[0], uw = 1.f - wgt;
    int ry = l & 3;
    float wy0 = c_wtab[ry], wy1 = 1.f - wy0;
    int yA = (l >> 2) + 1 + ((ry < 2) ? -1 : 0);
    float pool[Cn];
    #pragma unroll
    for (int c = 0; c < Cn; c++) pool[c] = 0.f;
    #pragma unroll
    for (int r = 0; r < 4; r++) {
        float wx0 = c_wtab[r], wx1 = 1.f - wx0;
        int xA = w + 1 + ((r < 2) ? -1 : 0);
        int base = xA*10 + yA;
        float v[Cn];
        float mmax = -1e30f;
        #pragma unroll
        for (int c = 0; c < Cn; c++) {
            const float* mc = m_s + c*100 + base;
            float mu = wx0*(wy0*mc[0] + wy1*mc[1]) + wx1*(wy0*mc[10] + wy1*mc[11]);
            float vv = uw * __ldg(up + (size_t)c*Hn*Wn + r*Wn) + wgt * mu;
            v[c] = vv;
            mmax = fmaxf(mmax, vv);
        }
        float s = 0.f;
        #pragma unroll
        for (int c = 0; c < Cn; c++) { v[c] = __expf(v[c] - mmax); s += v[c]; }
        float inv = 1.f / s;
        #pragma unroll
        for (int c = 0; c < Cn; c++) pool[c] += v[c] * inv;
    }
    int xp = (x0 >> 2) + XOFF;
    int yp = (Y  >> 2) + YOFF;
    #pragma unroll
    for (int c = 0; c < Cn; c++) {
        float r = pool[c];
        r += __shfl_xor_sync(0xffffffffu, r, 1);
        r += __shfl_xor_sync(0xffffffffu, r, 2);
        if ((l & 3) == 0)
            g_ppad[((size_t)(b*Cn + c)*PP + xp)*PP + yp] = r * 0.0625f;
    }
}

// ---------------------------------------------------------------------------
// 6) final (exact R7)
__global__ void k_final(const float* __restrict__ unary, const float* __restrict__ weight,
                        float* __restrict__ out) {
    __shared__ float m_s[Cn*100];
    int b = blockIdx.z;
    int t = threadIdx.x, w = t >> 5, l = t & 31;
    int lx0 = blockIdx.y*8 - 1, ly0 = blockIdx.x*8 - 1;
    for (int i = t; i < Cn*100; i += 256) {
        int c = i / 100, rem = i % 100;
        int xx = lx0 + rem/10; xx = max(0, min(HL-1, xx));
        int yy = ly0 + rem%10; yy = max(0, min(WL-1, yy));
        m_s[i] = g_msg[((b*Cn + c)*HL + xx)*WL + yy];
    }
    __syncthreads();
    int x0 = blockIdx.y*32 + w*4;
    int Y  = blockIdx.x*32 + l;
    const float* up   = unary + ((size_t)(b*Cn)*Hn + x0)*Wn + Y;
    float*       outp = out   + ((size_t)(b*Cn)*Hn + x0)*Wn + Y;
    float wgt = weight[0], uw = 1.f - wgt;
    int ry = l & 3;
    float wy0 = c_wtab[ry], wy1 = 1.f - wy0;
    int yA = (l >> 2) + 1 + ((ry < 2) ? -1 : 0);
    #pragma unroll
    for (int r = 0; r < 4; r++) {
        float wx0 = c_wtab[r], wx1 = 1.f - wx0;
        int xA = w + 1 + ((r < 2) ? -1 : 0);
        int base = xA*10 + yA;
        float u[Cn];
        float m = -1e30f;
        #pragma unroll
        for (int c = 0; c < Cn; c++) {
            u[c] = __ldg(up + (size_t)c*Hn*Wn + r*Wn);
            m = fmaxf(m, u[c]);
        }
        float s = 0.f;
        #pragma unroll
        for (int c = 0; c < Cn; c++) s += __expf(u[c] - m);
        float lse = m + logf(s);
        #pragma unroll
        for (int c = 0; c < Cn; c++) {
            const float* mc = m_s + c*100 + base;
            float mu = wx0*(wy0*mc[0] + wy1*mc[1]) + wx1*(wy0*mc[10] + wy1*mc[11]);
            outp[(size_t)c*Hn*Wn + r*Wn] = uw * (u[c] - lse) + wgt * mu;
        }
    }
}

// ---------------------------------------------------------------------------
extern "C" void kernel_launch(void* const* d_in, const int* in_sizes, int n_in,
                              void* d_out, int out_size) {
    const float* unary      = (const float*)d_in[0];
    const float* img        = (const float*)d_in[1];
    const float* pos_sdims  = (const float*)d_in[2];
    const float* col_schan  = (const float*)d_in[3];
    const float* pos_compat = (const float*)d_in[4];
    const float* col_compat = (const float*)d_in[5];
    const float* weight     = (const float*)d_in[6];
    float* out = (float*)d_out;

    static int smem_set = 0;
    if (!smem_set) {
        cudaFuncSetAttribute(k_msg, cudaFuncAttributeMaxDynamicSharedMemorySize,
                             GK_SMEM_BYTES);
        smem_set = 1;
    }

    k_zero<<<(Bn*Cn*PLANE/4 + 255)/256, 256>>>();
    k_pool_img<<<(Bn*3*HL*WL + 255)/256, 256>>>(img, col_schan);
    k_gauss<<<dim3(8, 16, Bn), 128>>>(pos_sdims, pos_compat, col_compat);
    k_init<<<dim3(16, 16, Bn), 256>>>(unary);
    for (int it = 0; it < 5; it++) {
        k_msg<<<dim3(8, 16, Bn), 224, GK_SMEM_BYTES>>>();
        if (it < 4)
            k_iter<<<dim3(16, 16, Bn), 256>>>(unary, weight);
        else
            k_final<<<dim3(16, 16, Bn), 256>>>(unary, weight, out);
    }
}